// round 15
// baseline (speedup 1.0000x reference)
#include <cuda_runtime.h>
#include <cuda_fp16.h>
#include <math.h>
#include <stdint.h>

// ---------------- problem constants ----------------
#define MAXN   20000
#define MAXE   400000
#define INCH   64
#define HID    512
#define NPRED  12
#define MT_MAX 1256          // padded row-tiles: 20096 rows

// ---------------- scratch buffers (device globals; no runtime alloc) ----------------
__device__ __align__(256) float  g_t    [MAXN * HID];
__device__ __align__(256) float  g_agg  [MAXN * HID];
__device__ __align__(256) float  g_gates[MAXN * 4 * HID];
__device__ __align__(256) float  g_c    [MAXN * HID];
__device__ __align__(256) float  g_ht   [MAXN * HID];
__device__ __align__(256) float  g_peep [MAXN * 2 * HID];
__device__ __align__(256) float  g_bnsums[2 * HID];
__device__ __align__(256) float  g_biaspk[1536];
// fragment-major fp16 A-operand buffers (padded; pad rows stay 0)
__device__ __align__(256) __half g_axh  [MT_MAX * 4  * 256];   // K=64
__device__ __align__(256) __half g_hh   [MT_MAX * 32 * 256];   // K=512
__device__ __align__(256) __half g_ch   [MT_MAX * 32 * 256];   // K=512
__device__ __align__(256) __half g_dual [MT_MAX * 64 * 256];   // K=1024: [h | ht]
// fragment-major fp16 weights
__device__ __align__(256) __half g_wt   [4751360];
// CSR
__device__ __align__(256) int    g_deg  [MAXN];
__device__ __align__(256) int    g_fill [MAXN];
__device__ __align__(256) int    g_rowptr[MAXN + 1];
__device__ __align__(256) int    g_esrc [MAXE];
__device__ __align__(256) float  g_ew2  [MAXE];

// weight offsets (halves)
#define WT_GCN0    0
#define WT_GCN1    32768
#define WT_GCN2    294912
#define WT_IH0     557056      // [i|g|o] 1536 cols
#define WT_IHHH1   1605632
#define WT_CH0_O   3702784
#define WT_CH1_FG  3964928
#define WT_CH1_O   4489216

// ---------------- side stream (created once, before harness checkpoints) ----------------
struct StreamHolder {
    cudaStream_t s = nullptr;
    cudaEvent_t evFork = nullptr, evJoin = nullptr;
    StreamHolder() {
        if (cudaStreamCreateWithFlags(&s, cudaStreamNonBlocking) != cudaSuccess) {
            s = nullptr;
            return;
        }
        if (cudaEventCreateWithFlags(&evFork, cudaEventDisableTiming) != cudaSuccess ||
            cudaEventCreateWithFlags(&evJoin, cudaEventDisableTiming) != cudaSuccess) {
            s = nullptr;
        }
    }
};
static StreamHolder g_sh;

// ---------------- fragment-major addressing ----------------
__device__ __forceinline__ size_t afrag(int m, int k, int Kt) {
    int lane = ((m & 7) << 2) | ((k >> 1) & 3);
    int w = ((m >> 3) & 1) | (((k >> 3) & 1) << 1);
    return ((((size_t)(m >> 4) * Kt + (k >> 4)) << 5) + (size_t)lane) * 8 + (w << 1);
}

__device__ __forceinline__ uint32_t smem_u32(const void* p) {
    uint32_t a;
    asm("{ .reg .u64 t; cvta.to.shared.u64 t, %1; cvt.u32.u64 %0, t; }" : "=r"(a) : "l"(p));
    return a;
}

__device__ __forceinline__ float sigmoidf_(float x) { return 1.f / (1.f + expf(-x)); }

// ---------------- fused weight pack: all segments in one launch ----------------
struct PackSeg {
    const float* W;
    int ldw, outOff, KtTot, ktBase, K, Nn, base;
};
struct PackArgs {
    PackSeg d[11];
    int total;
};

__global__ void packAll_kernel(PackArgs a, __half* __restrict__ out) {
    int idx = blockIdx.x * blockDim.x + threadIdx.x;
    if (idx >= a.total) return;
    int s = 0;
#pragma unroll
    for (int i = 1; i < 11; i++)
        if (idx >= a.d[i].base) s = i;
    PackSeg d = a.d[s];
    int l = idx - d.base;
    int lane = l & 31;
    int f = l >> 5;
    int KtS = d.K >> 4;
    int kt = f % KtS;
    int nt = f / KtS;
    int n = (nt << 3) + (lane >> 2);
    int k = (kt << 4) + ((lane & 3) << 1);
    const float* w0 = d.W + (size_t)k * d.ldw + n;
    __half2 lo = __floats2half2_rn(w0[0], w0[d.ldw]);
    __half2 hi = __floats2half2_rn(w0[(size_t)8 * d.ldw], w0[(size_t)9 * d.ldw]);
    size_t of = (size_t)d.outOff + (((size_t)nt * d.KtTot + d.ktBase + kt) * 32 + lane) * 4;
    *reinterpret_cast<__half2*>(out + of)     = lo;
    *reinterpret_cast<__half2*>(out + of + 2) = hi;
}

// packed layer-0 bias: [b_i | b_g | b_o]
__global__ void pack_bias_kernel(const float* __restrict__ b, float* __restrict__ pb) {
    int i = blockIdx.x * blockDim.x + threadIdx.x;
    if (i >= 1536) return;
    int srcoff = (i < 512) ? i : (i < 1024 ? 1024 + (i - 512) : 1536 + (i - 1024));
    pb[i] = b[srcoff];
}

// ---------------- CSR build ----------------
__global__ void zero2_int_kernel(int* __restrict__ a, int* __restrict__ b, int n) {
    int i = blockIdx.x * blockDim.x + threadIdx.x;
    if (i < n) { a[i] = 0; b[i] = 0; }
}

__global__ void hist_kernel(const int* __restrict__ dst, int* __restrict__ deg, int E) {
    int e = blockIdx.x * blockDim.x + threadIdx.x;
    if (e < E) atomicAdd(&deg[dst[e]], 1);
}

__global__ void scan_kernel(const int* __restrict__ deg, int* __restrict__ rowptr, int n) {
    __shared__ int warp_sums[32];
    __shared__ int carry_s;
    int tid = threadIdx.x;
    int lane = tid & 31, wid = tid >> 5;
    if (tid == 0) { carry_s = 0; rowptr[0] = 0; }
    __syncthreads();
    for (int base = 0; base < n; base += 1024) {
        int i = base + tid;
        int v = (i < n) ? deg[i] : 0;
        int x = v;
#pragma unroll
        for (int o = 1; o < 32; o <<= 1) {
            int y = __shfl_up_sync(0xFFFFFFFFu, x, o);
            if (lane >= o) x += y;
        }
        if (lane == 31) warp_sums[wid] = x;
        __syncthreads();
        if (wid == 0) {
            int s = warp_sums[lane];
#pragma unroll
            for (int o = 1; o < 32; o <<= 1) {
                int y = __shfl_up_sync(0xFFFFFFFFu, s, o);
                if (lane >= o) s += y;
            }
            warp_sums[lane] = s;
        }
        __syncthreads();
        int incl = x + (wid > 0 ? warp_sums[wid - 1] : 0) + carry_s;
        if (i < n) rowptr[i + 1] = incl;
        __syncthreads();
        if (tid == 1023) carry_s = incl;
        __syncthreads();
    }
}

__global__ void fill_kernel(const int* __restrict__ src, const int* __restrict__ dst,
                            const float* __restrict__ ew,
                            const int* __restrict__ rowptr, int* __restrict__ fill,
                            int* __restrict__ esrc, float* __restrict__ ew2, int E) {
    int e = blockIdx.x * blockDim.x + threadIdx.x;
    if (e >= E) return;
    int d = dst[e];
    int pos = rowptr[d] + atomicAdd(&fill[d], 1);
    esrc[pos] = src[e];
    ew2[pos]  = ew[e];
}

// ---------------- CSR aggregation (block 0 also zeroes bn sums) ----------------
__global__ __launch_bounds__(128)
void aggr512_kernel(const float* __restrict__ feat,
                    const int* __restrict__ rowptr, const int* __restrict__ esrc,
                    const float* __restrict__ ew2, float* __restrict__ out,
                    float* __restrict__ sums) {
    if (blockIdx.x == 0) {
        for (int i = threadIdx.x; i < 2 * HID; i += 128) sums[i] = 0.f;
    }
    int node = blockIdx.x;
    int col = threadIdx.x * 4;
    int beg = rowptr[node], end = rowptr[node + 1];
    float4 acc = make_float4(0.f, 0.f, 0.f, 0.f);
    int j = beg;
    for (; j + 1 < end; j += 2) {
        int s0 = esrc[j], s1 = esrc[j + 1];
        float w0 = ew2[j], w1 = ew2[j + 1];
        float4 v0 = *reinterpret_cast<const float4*>(feat + (size_t)s0 * HID + col);
        float4 v1 = *reinterpret_cast<const float4*>(feat + (size_t)s1 * HID + col);
        acc.x = fmaf(w0, v0.x, acc.x); acc.y = fmaf(w0, v0.y, acc.y);
        acc.z = fmaf(w0, v0.z, acc.z); acc.w = fmaf(w0, v0.w, acc.w);
        acc.x = fmaf(w1, v1.x, acc.x); acc.y = fmaf(w1, v1.y, acc.y);
        acc.z = fmaf(w1, v1.z, acc.z); acc.w = fmaf(w1, v1.w, acc.w);
    }
    if (j < end) {
        int s0 = esrc[j];
        float w0 = ew2[j];
        float4 v0 = *reinterpret_cast<const float4*>(feat + (size_t)s0 * HID + col);
        acc.x = fmaf(w0, v0.x, acc.x); acc.y = fmaf(w0, v0.y, acc.y);
        acc.z = fmaf(w0, v0.z, acc.z); acc.w = fmaf(w0, v0.w, acc.w);
    }
    *reinterpret_cast<float4*>(out + (size_t)node * HID + col) = acc;
}

__global__ __launch_bounds__(128)
void aggr64_kernel(const float* __restrict__ feat,
                   const int* __restrict__ rowptr, const int* __restrict__ esrc,
                   const float* __restrict__ ew2, __half* __restrict__ out, int N,
                   float* __restrict__ sums) {
    if (blockIdx.x == 0) {
        for (int i = threadIdx.x; i < 2 * HID; i += 128) sums[i] = 0.f;
    }
    int node = blockIdx.x * 8 + (threadIdx.x >> 4);
    if (node >= N) return;
    int col = (threadIdx.x & 15) * 4;
    int beg = rowptr[node], end = rowptr[node + 1];
    float4 acc = make_float4(0.f, 0.f, 0.f, 0.f);
    for (int j = beg; j < end; j++) {
        int s = esrc[j];
        float w = ew2[j];
        float4 v = *reinterpret_cast<const float4*>(feat + (size_t)s * INCH + col);
        acc.x = fmaf(w, v.x, acc.x); acc.y = fmaf(w, v.y, acc.y);
        acc.z = fmaf(w, v.z, acc.z); acc.w = fmaf(w, v.w, acc.w);
    }
    *reinterpret_cast<__half2*>(out + afrag(node, col,     4)) = __floats2half2_rn(acc.x, acc.y);
    *reinterpret_cast<__half2*>(out + afrag(node, col + 2, 4)) = __floats2half2_rn(acc.z, acc.w);
}

// ---------------- fp16 tensor-core GEMM, cp.async 3-stage ----------------
#define CP_A16(dst, src) asm volatile("cp.async.cg.shared.global [%0], [%1], 16;" :: "r"(dst), "l"(src))
#define CP_B8(dst, src)  asm volatile("cp.async.ca.shared.global [%0], [%1], 8;"  :: "r"(dst), "l"(src))
#define CP_COMMIT()      asm volatile("cp.async.commit_group;" ::: "memory")
#define CP_WAIT1()       asm volatile("cp.async.wait_group 1;" ::: "memory")

// ---- 128x128 CTA tile, 4 warps (Nc=512 GEMMs) ----
template <int MODE>   // 0 = plain, 1 = +bias
__global__ __launch_bounds__(128, 2)
void hgemm_kernel(const __half* __restrict__ A, const __half* __restrict__ Bt,
                  float* __restrict__ C, const float* __restrict__ bias,
                  int M, int Kt, int ldc) {
    __shared__ uint32_t As[3][16 * 128];
    __shared__ uint32_t Bs[3][32 * 64];

    const int tid  = threadIdx.x;
    const int lane = tid & 31;
    const int warp = tid >> 5;
    const int bm = blockIdx.y * 128;
    const int bn = blockIdx.x * 128;
    const int wm = (warp >> 1) * 64;
    const int wn = (warp & 1) * 64;
    const int mtBase = bm >> 4;
    const int ntBase = bn >> 3;
    const int T = Kt >> 1;

    float acc[4][8][4];
#pragma unroll
    for (int i = 0; i < 4; i++)
#pragma unroll
        for (int j = 0; j < 8; j++)
#pragma unroll
            for (int k = 0; k < 4; k++) acc[i][j][k] = 0.f;

    auto issue = [&](int t, int stage) {
#pragma unroll
        for (int it = 0; it < 4; it++) {
            int p = tid + it * 128;
            int fi = p >> 5, ln = p & 31;
            const __half* src = A + ((((size_t)(mtBase + (fi >> 1)) * Kt) + (2 * t + (fi & 1))) * 32 + ln) * 8;
            CP_A16(smem_u32(&As[stage][fi * 128 + ln * 4]), src);
        }
#pragma unroll
        for (int it = 0; it < 8; it++) {
            int p = tid + it * 128;
            int fi = p >> 5, ln = p & 31;
            const __half* src = Bt + ((((size_t)(ntBase + (fi >> 1)) * Kt) + (2 * t + (fi & 1))) * 32 + ln) * 4;
            CP_B8(smem_u32(&Bs[stage][fi * 64 + ln * 2]), src);
        }
    };
    auto compute = [&](int buf) {
#pragma unroll
        for (int kt = 0; kt < 2; kt++) {
            uint32_t af[4][4];
#pragma unroll
            for (int mi = 0; mi < 4; mi++) {
                int fi = ((wm >> 4) + mi) * 2 + kt;
                uint4 v = *reinterpret_cast<const uint4*>(&As[buf][fi * 128 + lane * 4]);
                af[mi][0] = v.x; af[mi][1] = v.y; af[mi][2] = v.z; af[mi][3] = v.w;
            }
            uint32_t bf[8][2];
#pragma unroll
            for (int ni = 0; ni < 8; ni++) {
                int fi = ((wn >> 3) + ni) * 2 + kt;
                uint2 v = *reinterpret_cast<const uint2*>(&Bs[buf][fi * 64 + lane * 2]);
                bf[ni][0] = v.x; bf[ni][1] = v.y;
            }
#pragma unroll
            for (int mi = 0; mi < 4; mi++)
#pragma unroll
                for (int ni = 0; ni < 8; ni++) {
                    asm volatile(
                        "mma.sync.aligned.m16n8k16.row.col.f32.f16.f16.f32 "
                        "{%0,%1,%2,%3}, {%4,%5,%6,%7}, {%8,%9}, {%0,%1,%2,%3};\n"
                        : "+f"(acc[mi][ni][0]), "+f"(acc[mi][ni][1]),
                          "+f"(acc[mi][ni][2]), "+f"(acc[mi][ni][3])
                        : "r"(af[mi][0]), "r"(af[mi][1]), "r"(af[mi][2]), "r"(af[mi][3]),
                          "r"(bf[ni][0]), "r"(bf[ni][1]));
                }
        }
    };

    issue(0, 0);
    CP_COMMIT();
    if (T > 1) issue(1, 1);
    CP_COMMIT();
    for (int t = 0; t < T; t++) {
        CP_WAIT1();
        __syncthreads();
        if (t + 2 < T) issue(t + 2, (t + 2) % 3);
        CP_COMMIT();
        compute(t % 3);
    }

    const int gq = lane >> 2;
    const int rr = (lane & 3) << 1;
#pragma unroll
    for (int mi = 0; mi < 4; mi++) {
#pragma unroll
        for (int ni = 0; ni < 8; ni++) {
            int col = bn + wn + ni * 8 + rr;
#pragma unroll
            for (int h = 0; h < 2; h++) {
                int r = bm + wm + mi * 16 + gq + h * 8;
                if (r < M) {
                    float2 v = make_float2(acc[mi][ni][h * 2], acc[mi][ni][h * 2 + 1]);
                    if (MODE == 1) { v.x += bias[col]; v.y += bias[col + 1]; }
                    *reinterpret_cast<float2*>(C + (size_t)r * ldc + col) = v;
                }
            }
        }
    }
}

// ---- 128x256 CTA tile, 8 warps, dynamic smem (wide GEMMs; halves A L2 traffic) ----
template <int MODE>   // 0 = plain, 1 = +bias
__global__ __launch_bounds__(256, 1)
void hgemm256_kernel(const __half* __restrict__ A, const __half* __restrict__ Bt,
                     float* __restrict__ C, const float* __restrict__ bias,
                     int M, int Kt, int ldc) {
    extern __shared__ uint32_t sm[];
    uint32_t* As = sm;              // [3][16*128] = 6144 u32
    uint32_t* Bs = sm + 3 * 2048;   // [3][64*64]  = 12288 u32

    const int tid  = threadIdx.x;
    const int lane = tid & 31;
    const int warp = tid >> 5;          // 0..7
    const int bm = blockIdx.y * 128;
    const int bn = blockIdx.x * 256;
    const int wm = (warp >> 2) * 64;    // 0 or 64
    const int wn = (warp & 3) * 64;     // 0,64,128,192
    const int mtBase = bm >> 4;
    const int ntBase = bn >> 3;
    const int T = Kt >> 1;

    float acc[4][8][4];
#pragma unroll
    for (int i = 0; i < 4; i++)
#pragma unroll
        for (int j = 0; j < 8; j++)
#pragma unroll
            for (int k = 0; k < 4; k++) acc[i][j][k] = 0.f;

    auto issue = [&](int t, int stage) {
#pragma unroll
        for (int it = 0; it < 2; it++) {
            int p = tid + it * 256;
            int fi = p >> 5, ln = p & 31;
            const __half* src = A + ((((size_t)(mtBase + (fi >> 1)) * Kt) + (2 * t + (fi & 1))) * 32 + ln) * 8;
            CP_A16(smem_u32(&As[stage * 2048 + fi * 128 + ln * 4]), src);
        }
#pragma unroll
        for (int it = 0; it < 8; it++) {
            int p = tid + it * 256;
            int fi = p >> 5, ln = p & 31;
            const __half* src = Bt + ((((size_t)(ntBase + (fi >> 1)) * Kt) + (2 * t + (fi & 1))) * 32 + ln) * 4;
            CP_B8(smem_u32(&Bs[stage * 4096 + fi * 64 + ln * 2]), src);
        }
    };
    auto compute = [&](int buf) {
#pragma unroll
        for (int kt = 0; kt < 2; kt++) {
            uint32_t af[4][4];
#pragma unroll
            for (int mi = 0; mi < 4; mi++) {
                int fi = ((wm >> 4) + mi) * 2 + kt;
                uint4 v = *reinterpret_cast<const uint4*>(&As[buf * 2048 + fi * 128 + lane * 4]);
                af[mi][0] = v.x; af[mi][1] = v.y; af[mi][2] = v.z; af[mi][3] = v.w;
            }
            uint32_t bf[8][2];
#pragma unroll
            for (int ni = 0; ni < 8; ni++) {
                int fi = ((wn >> 3) + ni) * 2 + kt;
                uint2 v = *reinterpret_cast<const uint2*>(&Bs[buf * 4096 + fi * 64 + lane * 2]);
                bf[ni][0] = v.x; bf[ni][1] = v.y;
            }
#pragma unroll
            for (int mi = 0; mi < 4; mi++)
#pragma unroll
                for (int ni = 0; ni < 8; ni++) {
                    asm volatile(
                        "mma.sync.aligned.m16n8k16.row.col.f32.f16.f16.f32 "
                        "{%0,%1,%2,%3}, {%4,%5,%6,%7}, {%8,%9}, {%0,%1,%2,%3};\n"
                        : "+f"(acc[mi][ni][0]), "+f"(acc[mi][ni][1]),
                          "+f"(acc[mi][ni][2]), "+f"(acc[mi][ni][3])
                        : "r"(af[mi][0]), "r"(af[mi][1]), "r"(af[mi][2]), "r"(af[mi][3]),
                          "r"(bf[ni][0]), "r"(bf[ni][1]));
                }
        }
    };

    issue(0, 0);
    CP_COMMIT();
    if (T > 1) issue(1, 1);
    CP_COMMIT();
    for (int t = 0; t < T; t++) {
        CP_WAIT1();
        __syncthreads();
        if (t + 2 < T) issue(t + 2, (t + 2) % 3);
        CP_COMMIT();
        compute(t % 3);
    }

    const int gq = lane >> 2;
    const int rr = (lane & 3) << 1;
#pragma unroll
    for (int mi = 0; mi < 4; mi++) {
#pragma unroll
        for (int ni = 0; ni < 8; ni++) {
            int col = bn + wn + ni * 8 + rr;
#pragma unroll
            for (int h = 0; h < 2; h++) {
                int r = bm + wm + mi * 16 + gq + h * 8;
                if (r < M) {
                    float2 v = make_float2(acc[mi][ni][h * 2], acc[mi][ni][h * 2 + 1]);
                    if (MODE == 1) { v.x += bias[col]; v.y += bias[col + 1]; }
                    *reinterpret_cast<float2*>(C + (size_t)r * ldc + col) = v;
                }
            }
        }
    }
}

#define HG256_SMEM ((3 * 2048 + 3 * 4096) * 4)

// ---------------- BN / elementwise ----------------
__global__ void bn_stats_kernel(const float* __restrict__ x, float* __restrict__ sums,
                                int Nrows, int C) {
    int col = threadIdx.x;
    int rowsPerBlock = (Nrows + gridDim.x - 1) / gridDim.x;
    int r0 = blockIdx.x * rowsPerBlock;
    int r1 = min(Nrows, r0 + rowsPerBlock);
    float s = 0.f, s2 = 0.f;
    for (int r = r0; r < r1; r++) {
        float v = x[(size_t)r * C + col];
        s += v;
        s2 = fmaf(v, v, s2);
    }
    atomicAdd(&sums[col], s);
    atomicAdd(&sums[C + col], s2);
}

__global__ void bn_apply_relu_kernel(const float* __restrict__ x,
                                     __half* __restrict__ hh, __half* __restrict__ dual,
                                     const float* __restrict__ sums,
                                     const float* __restrict__ gamma,
                                     const float* __restrict__ beta,
                                     int N, float invN) {
    int idx = blockIdx.x * blockDim.x + threadIdx.x;
    if (idx >= N * 256) return;
    int row = idx >> 8;
    int col = (idx & 255) << 1;
    float2 xv = reinterpret_cast<const float2*>(x)[idx];
    float mu0  = sums[col] * invN,  mu1 = sums[col + 1] * invN;
    float var0 = sums[HID + col] * invN - mu0 * mu0;
    float var1 = sums[HID + col + 1] * invN - mu1 * mu1;
    float v0 = (xv.x - mu0) * (gamma[col] * rsqrtf(var0 + 1e-5f)) + beta[col];
    float v1 = (xv.y - mu1) * (gamma[col + 1] * rsqrtf(var1 + 1e-5f)) + beta[col + 1];
    __half2 h = __floats2half2_rn(fmaxf(v0, 0.f), fmaxf(v1, 0.f));
    *reinterpret_cast<__half2*>(hh + afrag(row, col, 32)) = h;
    if (dual) *reinterpret_cast<__half2*>(dual + afrag(row, col, 64)) = h;
}

// layer0: gates layout [i|g|o] stride 1536; c = sigmoid(i)*tanh(g)
__global__ void cell0a_kernel(const float* __restrict__ gates, float* __restrict__ c,
                              __half* __restrict__ ch, int N) {
    int idx = blockIdx.x * blockDim.x + threadIdx.x;
    if (idx >= N * 256) return;
    int row = idx >> 8;
    int col = (idx & 255) << 1;
    const float* g = gates + (size_t)row * 1536;
    float2 iv = *reinterpret_cast<const float2*>(g + col);
    float2 gv = *reinterpret_cast<const float2*>(g + 512 + col);
    float v0 = sigmoidf_(iv.x) * tanhf(gv.x);
    float v1 = sigmoidf_(iv.y) * tanhf(gv.y);
    *reinterpret_cast<float2*>(c + (size_t)row * HID + col) = make_float2(v0, v1);
    *reinterpret_cast<__half2*>(ch + afrag(row, col, 32)) = __floats2half2_rn(v0, v1);
}

// ht = sigmoid(o + opeep) * tanh(c); og = o-gate base, ldg = gate row stride
template <int L>
__global__ void cell_ob_kernel(const float* __restrict__ og, int ldg,
                               const float* __restrict__ op, const float* __restrict__ c,
                               float* __restrict__ ht, __half* __restrict__ dual, int N) {
    int idx = blockIdx.x * blockDim.x + threadIdx.x;
    if (idx >= N * 256) return;
    int row = idx >> 8;
    int col = (idx & 255) << 1;
    float2 ov = *reinterpret_cast<const float2*>(og + (size_t)row * ldg + col);
    float2 pv = *reinterpret_cast<const float2*>(op + (size_t)row * HID + col);
    float2 cv = *reinterpret_cast<const float2*>(c + (size_t)row * HID + col);
    float v0 = sigmoidf_(ov.x + pv.x) * tanhf(cv.x);
    float v1 = sigmoidf_(ov.y + pv.y) * tanhf(cv.y);
    if (L == 0)
        *reinterpret_cast<__half2*>(dual + afrag(row, 512 + col, 64)) = __floats2half2_rn(v0, v1);
    else
        *reinterpret_cast<float2*>(ht + (size_t)row * HID + col) = make_float2(v0, v1);
}

// layer1: c <- f*c + i*g (with peepholes); write c fp32 + ch fp16
__global__ void cell1a_kernel(const float* __restrict__ gates, const float* __restrict__ cp,
                              float* __restrict__ c, __half* __restrict__ ch, int N) {
    int idx = blockIdx.x * blockDim.x + threadIdx.x;
    if (idx >= N * 256) return;
    int row = idx >> 8;
    int col = (idx & 255) << 1;
    const float* g = gates + (size_t)row * 2048;
    float2 iv = *reinterpret_cast<const float2*>(g + col);
    float2 fv = *reinterpret_cast<const float2*>(g + 512 + col);
    float2 gv = *reinterpret_cast<const float2*>(g + 1024 + col);
    float2 pg = *reinterpret_cast<const float2*>(cp + (size_t)row * 1024 + col);
    float2 pf = *reinterpret_cast<const float2*>(cp + (size_t)row * 1024 + 512 + col);
    float2 cv = *reinterpret_cast<const float2*>(c + (size_t)row * HID + col);
    float v0 = sigmoidf_(fv.x + pf.x) * cv.x + sigmoidf_(iv.x) * tanhf(gv.x + pg.x);
    float v1 = sigmoidf_(fv.y + pf.y) * cv.y + sigmoidf_(iv.y) * tanhf(gv.y + pg.y);
    *reinterpret_cast<float2*>(c + (size_t)row * HID + col) = make_float2(v0, v1);
    *reinterpret_cast<__half2*>(ch + afrag(row, col, 32)) = __floats2half2_rn(v0, v1);
}

// ---------------- output projection: warp per row, B transposed in smem ----------------
__global__ __launch_bounds__(256)
void outproj_kernel(const float* __restrict__ A, const float* __restrict__ B,
                    float* __restrict__ C, const float* __restrict__ bias, int M) {
    __shared__ float Bs[NPRED * HID];
    int tid = threadIdx.x;
    for (int i = tid; i < NPRED * HID; i += 256) {
        int k = i / NPRED, c = i % NPRED;
        Bs[c * HID + k] = B[i];
    }
    __syncthreads();
    int warp = tid >> 5, lane = tid & 31;
    int row = blockIdx.x * 8 + warp;
    if (row >= M) return;
    const float* a = A + (size_t)row * HID;
    float acc[NPRED];
#pragma unroll
    for (int c = 0; c < NPRED; c++) acc[c] = 0.f;
#pragma unroll
    for (int kk = 0; kk < 16; kk++) {
        int k = kk * 32 + lane;
        float av = a[k];
#pragma unroll
        for (int c = 0; c < NPRED; c++)
            acc[c] = fmaf(av, Bs[c * HID + k], acc[c]);
    }
#pragma unroll
    for (int c = 0; c < NPRED; c++)
#pragma unroll
        for (int o = 16; o > 0; o >>= 1)
            acc[c] += __shfl_down_sync(0xFFFFFFFFu, acc[c], o);
    if (lane == 0) {
#pragma unroll
        for (int c = 0; c < NPRED; c++)
            C[(size_t)row * NPRED + c] = acc[c] + bias[c];
    }
}

// ---------------- host orchestration ----------------
static inline void run_hgemm(const __half* A, const __half* Bt, float* C, const float* bias,
                             int M, int Nc, int Kt, int ldc, int mode) {
    dim3 grid(Nc / 128, (M + 127) / 128);
    if (mode == 1)
        hgemm_kernel<1><<<grid, 128>>>(A, Bt, C, bias, M, Kt, ldc);
    else
        hgemm_kernel<0><<<grid, 128>>>(A, Bt, C, bias, M, Kt, ldc);
}

static inline void run_hgemm256(const __half* A, const __half* Bt, float* C, const float* bias,
                                int M, int Nc, int Kt, int ldc, int mode) {
    dim3 grid(Nc / 256, (M + 127) / 128);
    if (mode == 1)
        hgemm256_kernel<1><<<grid, 256, HG256_SMEM>>>(A, Bt, C, bias, M, Kt, ldc);
    else
        hgemm256_kernel<0><<<grid, 256, HG256_SMEM>>>(A, Bt, C, bias, M, Kt, ldc);
}

extern "C" void kernel_launch(void* const* d_in, const int* in_sizes, int n_in,
                              void* d_out, int out_size) {
    const float* x        = (const float*)d_in[0];
    const int*   ei       = (const int*)  d_in[1];
    const float* ew       = (const float*)d_in[2];
    const float* gcn0_W   = (const float*)d_in[3];
    const float* gcn_W    = (const float*)d_in[5];
    const float* bn_gamma = (const float*)d_in[7];
    const float* bn_beta  = (const float*)d_in[8];
    const float* w_ih     = (const float*)d_in[9];
    const float* w_hh     = (const float*)d_in[10];
    const float* w_ch     = (const float*)d_in[11];
    const float* lstm_b   = (const float*)d_in[12];
    const float* out_W    = (const float*)d_in[13];
    const float* out_b    = (const float*)d_in[14];
    float* out = (float*)d_out;

    cudaFuncSetAttribute(hgemm256_kernel<0>, cudaFuncAttributeMaxDynamicSharedMemorySize, HG256_SMEM);
    cudaFuncSetAttribute(hgemm256_kernel<1>, cudaFuncAttributeMaxDynamicSharedMemorySize, HG256_SMEM);

    const int N = in_sizes[0] / INCH;
    const int E = in_sizes[2];
    const int* src = ei;
    const int* dst = ei + E;
    const float invN = 1.f / (float)N;

    float *p_t, *p_agg, *p_gates, *p_c, *p_ht, *p_peep, *p_sums, *p_ew2, *p_biaspk;
    __half *p_wt, *p_axh, *p_hh, *p_ch, *p_dual;
    int *p_deg, *p_fill, *p_rowptr, *p_esrc;
    cudaGetSymbolAddress((void**)&p_t,     g_t);
    cudaGetSymbolAddress((void**)&p_agg,   g_agg);
    cudaGetSymbolAddress((void**)&p_gates, g_gates);
    cudaGetSymbolAddress((void**)&p_c,     g_c);
    cudaGetSymbolAddress((void**)&p_ht,    g_ht);
    cudaGetSymbolAddress((void**)&p_peep,  g_peep);
    cudaGetSymbolAddress((void**)&p_sums,  g_bnsums);
    cudaGetSymbolAddress((void**)&p_biaspk,g_biaspk);
    cudaGetSymbolAddress((void**)&p_wt,    g_wt);
    cudaGetSymbolAddress((void**)&p_axh,   g_axh);
    cudaGetSymbolAddress((void**)&p_hh,    g_hh);
    cudaGetSymbolAddress((void**)&p_ch,    g_ch);
    cudaGetSymbolAddress((void**)&p_dual,  g_dual);
    cudaGetSymbolAddress((void**)&p_deg,   g_deg);
    cudaGetSymbolAddress((void**)&p_fill,  g_fill);
    cudaGetSymbolAddress((void**)&p_rowptr,g_rowptr);
    cudaGetSymbolAddress((void**)&p_esrc,  g_esrc);
    cudaGetSymbolAddress((void**)&p_ew2,   g_ew2);

    const int blkNH2 = (N * 256 + 255) / 256;
    const int bnStatBlocks = 160;
    const int eBlocks = (E + 255) / 256;
    const float* wch1 = w_ch + (size_t)HID * 3 * HID;

    // ---- build fused pack descriptor table ----
    PackArgs pa;
    {
        int b = 0, i = 0;
        auto seg = [&](const float* W, int ldw, int outOff, int KtTot, int ktBase,
                       int K, int Nn) {
            pa.d[i++] = {W, ldw, outOff, KtTot, ktBase, K, Nn, b};
            b += Nn * K / 4;
        };
        seg(gcn0_W, HID, WT_GCN0, 4, 0, INCH, 512);
        seg(gcn_W,             HID, WT_GCN1, 32, 0, HID, 512);
        seg(gcn_W + HID * HID, HID, WT_GCN2, 32, 0, HID, 512);
        seg(w_ih,        4 * HID, WT_IH0,              32, 0, HID, 512);
        seg(w_ih + 1024, 4 * HID, WT_IH0 + 64 * 4096,  32, 0, HID, 512);
        seg(w_ih + 1536, 4 * HID, WT_IH0 + 128 * 4096, 32, 0, HID, 512);
        seg(w_ih + (size_t)HID * 4 * HID, 4 * HID, WT_IHHH1, 64, 0,  HID, 4 * HID);
        seg(w_hh + (size_t)HID * 4 * HID, 4 * HID, WT_IHHH1, 64, 32, HID, 4 * HID);
        seg(w_ch + 2 * HID, 3 * HID, WT_CH0_O,  32, 0, HID, 512);
        seg(wch1,           3 * HID, WT_CH1_FG, 32, 0, HID, 1024);
        seg(wch1 + 2 * HID, 3 * HID, WT_CH1_O,  32, 0, HID, 512);
        pa.total = b;
    }
    const int packBlocks = (pa.total + 255) / 256;
    const bool dual_stream = (g_sh.s != nullptr);

    // ---- fork: weight packs on side stream, CSR + aggr64 on main ----
    if (dual_stream) {
        cudaEventRecord(g_sh.evFork, 0);
        cudaStreamWaitEvent(g_sh.s, g_sh.evFork, 0);
        packAll_kernel<<<packBlocks, 256, 0, g_sh.s>>>(pa, p_wt);
        pack_bias_kernel<<<6, 256, 0, g_sh.s>>>(lstm_b, p_biaspk);
    } else {
        packAll_kernel<<<packBlocks, 256>>>(pa, p_wt);
        pack_bias_kernel<<<6, 256>>>(lstm_b, p_biaspk);
    }

    // CSR build + input aggregation (main stream)
    zero2_int_kernel<<<(N + 255) / 256, 256>>>(p_deg, p_fill, N);
    hist_kernel<<<eBlocks, 256>>>(dst, p_deg, E);
    scan_kernel<<<1, 1024>>>(p_deg, p_rowptr, N);
    fill_kernel<<<eBlocks, 256>>>(src, dst, ew, p_rowptr, p_fill, p_esrc, p_ew2, E);
    aggr64_kernel<<<(N + 7) / 8, 128>>>(x, p_rowptr, p_esrc, p_ew2, p_axh, N, p_sums);

    if (dual_stream) {
        cudaEventRecord(g_sh.evJoin, g_sh.s);
        cudaStreamWaitEvent(0, g_sh.evJoin, 0);
    }

    // ---- GCN layer 0 ----
    run_hgemm(p_axh, p_wt + WT_GCN0, p_t, nullptr, N, HID, 4, HID, 0);
    bn_stats_kernel<<<bnStatBlocks, HID>>>(p_t, p_sums, N, HID);
    bn_apply_relu_kernel<<<blkNH2, 256>>>(p_t, p_hh, nullptr, p_sums,
                                          bn_gamma, bn_beta, N, invN);

    // ---- GCN layers 1..2 ----
    for (int l = 0; l < 2; l++) {
        run_hgemm(p_hh, p_wt + (l == 0 ? WT_GCN1 : WT_GCN2), p_t, nullptr, N, HID, 32, HID, 0);
        aggr512_kernel<<<N, 128>>>(p_t, p_rowptr, p_esrc, p_ew2, p_agg, p_sums);
        bn_stats_kernel<<<bnStatBlocks, HID>>>(p_agg, p_sums, N, HID);
        bn_apply_relu_kernel<<<blkNH2, 256>>>(p_agg, p_hh, (l == 1) ? p_dual : nullptr,
                                              p_sums, bn_gamma + (l + 1) * HID,
                                              bn_beta + (l + 1) * HID, N, invN);
    }

    // ---- LSTM layer 0 (h0 = c0 = 0; gates [i|g|o], f skipped) ----
    run_hgemm256(p_hh, p_wt + WT_IH0, p_gates, p_biaspk, N, 1536, 32, 1536, 1);
    cell0a_kernel<<<blkNH2, 256>>>(p_gates, p_c, p_ch, N);
    run_hgemm(p_ch, p_wt + WT_CH0_O, p_peep, nullptr, N, HID, 32, HID, 0);
    cell_ob_kernel<0><<<blkNH2, 256>>>(p_gates + 1024, 1536, p_peep, p_c,
                                       nullptr, p_dual, N);

    // ---- LSTM layer 1 (fused [h|ht] @ [Wih1;Whh1], K=1024) ----
    run_hgemm256(p_dual, p_wt + WT_IHHH1, p_gates, lstm_b + 4 * HID, N, 4 * HID, 64, 4 * HID, 1);
    run_hgemm256(p_ch,   p_wt + WT_CH1_FG, p_peep, nullptr, N, 2 * HID, 32, 2 * HID, 0);
    cell1a_kernel<<<blkNH2, 256>>>(p_gates, p_peep, p_c, p_ch, N);
    run_hgemm(p_ch,   p_wt + WT_CH1_O, p_peep, nullptr, N, HID, 32, HID, 0);
    cell_ob_kernel<1><<<blkNH2, 256>>>(p_gates + 1536, 2048, p_peep, p_c,
                                       p_ht, nullptr, N);

    // ---- output projection ----
    outproj_kernel<<<(N + 7) / 8, 256>>>(p_ht, out_W, out, out_b, N);
}

// round 16
// speedup vs baseline: 1.0920x; 1.0920x over previous
#include <cuda_runtime.h>
#include <cuda_fp16.h>
#include <math.h>
#include <stdint.h>

// ---------------- problem constants ----------------
#define MAXN   20000
#define MAXE   400000
#define INCH   64
#define HID    512
#define NPRED  12
#define MT_MAX 1256          // padded row-tiles: 20096 rows

// ---------------- scratch buffers (device globals; no runtime alloc) ----------------
__device__ __align__(256) float  g_t    [MAXN * HID];
__device__ __align__(256) float  g_agg  [MAXN * HID];
__device__ __align__(256) float  g_gates[MAXN * 4 * HID];
__device__ __align__(256) float  g_c    [MAXN * HID];
__device__ __align__(256) float  g_ht   [MAXN * HID];
__device__ __align__(256) float  g_peep [MAXN * 2 * HID];
__device__ __align__(256) float  g_bnsums[2 * HID];
__device__ __align__(256) float  g_biaspk[1536];
// fragment-major fp16 A-operand buffers (padded; pad rows stay 0)
__device__ __align__(256) __half g_axh  [MT_MAX * 4  * 256];   // K=64
__device__ __align__(256) __half g_hh   [MT_MAX * 32 * 256];   // K=512
__device__ __align__(256) __half g_ch   [MT_MAX * 32 * 256];   // K=512
__device__ __align__(256) __half g_dual [MT_MAX * 64 * 256];   // K=1024: [h | ht]
// fragment-major fp16 weights
__device__ __align__(256) __half g_wt   [4751360];
// CSR
__device__ __align__(256) int    g_deg  [MAXN];
__device__ __align__(256) int    g_fill [MAXN];
__device__ __align__(256) int    g_rowptr[MAXN + 1];
__device__ __align__(256) int    g_esrc [MAXE];
__device__ __align__(256) float  g_ew2  [MAXE];

// weight offsets (halves)
#define WT_GCN0    0
#define WT_GCN1    32768
#define WT_GCN2    294912
#define WT_IH0     557056      // [i|g|o] 1536 cols
#define WT_IHHH1   1605632
#define WT_CH0_O   3702784
#define WT_CH1_FG  3964928
#define WT_CH1_O   4489216

// ---------------- side stream (created once, before harness checkpoints) ----------------
struct StreamHolder {
    cudaStream_t s = nullptr;
    cudaEvent_t evFork = nullptr, evJoin = nullptr, evFork2 = nullptr, evJoin2 = nullptr;
    StreamHolder() {
        if (cudaStreamCreateWithFlags(&s, cudaStreamNonBlocking) != cudaSuccess) {
            s = nullptr;
            return;
        }
        if (cudaEventCreateWithFlags(&evFork,  cudaEventDisableTiming) != cudaSuccess ||
            cudaEventCreateWithFlags(&evJoin,  cudaEventDisableTiming) != cudaSuccess ||
            cudaEventCreateWithFlags(&evFork2, cudaEventDisableTiming) != cudaSuccess ||
            cudaEventCreateWithFlags(&evJoin2, cudaEventDisableTiming) != cudaSuccess) {
            s = nullptr;
        }
    }
};
static StreamHolder g_sh;

// ---------------- fragment-major addressing ----------------
__device__ __forceinline__ size_t afrag(int m, int k, int Kt) {
    int lane = ((m & 7) << 2) | ((k >> 1) & 3);
    int w = ((m >> 3) & 1) | (((k >> 3) & 1) << 1);
    return ((((size_t)(m >> 4) * Kt + (k >> 4)) << 5) + (size_t)lane) * 8 + (w << 1);
}

__device__ __forceinline__ uint32_t smem_u32(const void* p) {
    uint32_t a;
    asm("{ .reg .u64 t; cvta.to.shared.u64 t, %1; cvt.u32.u64 %0, t; }" : "=r"(a) : "l"(p));
    return a;
}

__device__ __forceinline__ float sigmoidf_(float x) { return 1.f / (1.f + expf(-x)); }

// ---------------- fused weight pack: all segments in one launch ----------------
struct PackSeg {
    const float* W;
    int ldw, outOff, KtTot, ktBase, K, Nn, base;
};
struct PackArgs {
    PackSeg d[11];
    int total;
};

__global__ void packAll_kernel(PackArgs a, __half* __restrict__ out) {
    int idx = blockIdx.x * blockDim.x + threadIdx.x;
    if (idx >= a.total) return;
    int s = 0;
#pragma unroll
    for (int i = 1; i < 11; i++)
        if (idx >= a.d[i].base) s = i;
    PackSeg d = a.d[s];
    int l = idx - d.base;
    int lane = l & 31;
    int f = l >> 5;
    int KtS = d.K >> 4;
    int kt = f % KtS;
    int nt = f / KtS;
    int n = (nt << 3) + (lane >> 2);
    int k = (kt << 4) + ((lane & 3) << 1);
    const float* w0 = d.W + (size_t)k * d.ldw + n;
    __half2 lo = __floats2half2_rn(w0[0], w0[d.ldw]);
    __half2 hi = __floats2half2_rn(w0[(size_t)8 * d.ldw], w0[(size_t)9 * d.ldw]);
    size_t of = (size_t)d.outOff + (((size_t)nt * d.KtTot + d.ktBase + kt) * 32 + lane) * 4;
    *reinterpret_cast<__half2*>(out + of)     = lo;
    *reinterpret_cast<__half2*>(out + of + 2) = hi;
}

// packed layer-0 bias: [b_i | b_g | b_o]
__global__ void pack_bias_kernel(const float* __restrict__ b, float* __restrict__ pb) {
    int i = blockIdx.x * blockDim.x + threadIdx.x;
    if (i >= 1536) return;
    int srcoff = (i < 512) ? i : (i < 1024 ? 1024 + (i - 512) : 1536 + (i - 1024));
    pb[i] = b[srcoff];
}

// ---------------- CSR build ----------------
__global__ void zero2_int_kernel(int* __restrict__ a, int* __restrict__ b, int n) {
    int i = blockIdx.x * blockDim.x + threadIdx.x;
    if (i < n) { a[i] = 0; b[i] = 0; }
}

__global__ void hist_kernel(const int* __restrict__ dst, int* __restrict__ deg, int E) {
    int e = blockIdx.x * blockDim.x + threadIdx.x;
    if (e < E) atomicAdd(&deg[dst[e]], 1);
}

__global__ void scan_kernel(const int* __restrict__ deg, int* __restrict__ rowptr, int n) {
    __shared__ int warp_sums[32];
    __shared__ int carry_s;
    int tid = threadIdx.x;
    int lane = tid & 31, wid = tid >> 5;
    if (tid == 0) { carry_s = 0; rowptr[0] = 0; }
    __syncthreads();
    for (int base = 0; base < n; base += 1024) {
        int i = base + tid;
        int v = (i < n) ? deg[i] : 0;
        int x = v;
#pragma unroll
        for (int o = 1; o < 32; o <<= 1) {
            int y = __shfl_up_sync(0xFFFFFFFFu, x, o);
            if (lane >= o) x += y;
        }
        if (lane == 31) warp_sums[wid] = x;
        __syncthreads();
        if (wid == 0) {
            int s = warp_sums[lane];
#pragma unroll
            for (int o = 1; o < 32; o <<= 1) {
                int y = __shfl_up_sync(0xFFFFFFFFu, s, o);
                if (lane >= o) s += y;
            }
            warp_sums[lane] = s;
        }
        __syncthreads();
        int incl = x + (wid > 0 ? warp_sums[wid - 1] : 0) + carry_s;
        if (i < n) rowptr[i + 1] = incl;
        __syncthreads();
        if (tid == 1023) carry_s = incl;
        __syncthreads();
    }
}

__global__ void fill_kernel(const int* __restrict__ src, const int* __restrict__ dst,
                            const float* __restrict__ ew,
                            const int* __restrict__ rowptr, int* __restrict__ fill,
                            int* __restrict__ esrc, float* __restrict__ ew2, int E) {
    int e = blockIdx.x * blockDim.x + threadIdx.x;
    if (e >= E) return;
    int d = dst[e];
    int pos = rowptr[d] + atomicAdd(&fill[d], 1);
    esrc[pos] = src[e];
    ew2[pos]  = ew[e];
}

// ---------------- CSR aggregation (block 0 also zeroes bn sums) ----------------
__global__ __launch_bounds__(128)
void aggr512_kernel(const float* __restrict__ feat,
                    const int* __restrict__ rowptr, const int* __restrict__ esrc,
                    const float* __restrict__ ew2, float* __restrict__ out,
                    float* __restrict__ sums) {
    if (blockIdx.x == 0) {
        for (int i = threadIdx.x; i < 2 * HID; i += 128) sums[i] = 0.f;
    }
    int node = blockIdx.x;
    int col = threadIdx.x * 4;
    int beg = rowptr[node], end = rowptr[node + 1];
    float4 acc = make_float4(0.f, 0.f, 0.f, 0.f);
    int j = beg;
    for (; j + 1 < end; j += 2) {
        int s0 = esrc[j], s1 = esrc[j + 1];
        float w0 = ew2[j], w1 = ew2[j + 1];
        float4 v0 = *reinterpret_cast<const float4*>(feat + (size_t)s0 * HID + col);
        float4 v1 = *reinterpret_cast<const float4*>(feat + (size_t)s1 * HID + col);
        acc.x = fmaf(w0, v0.x, acc.x); acc.y = fmaf(w0, v0.y, acc.y);
        acc.z = fmaf(w0, v0.z, acc.z); acc.w = fmaf(w0, v0.w, acc.w);
        acc.x = fmaf(w1, v1.x, acc.x); acc.y = fmaf(w1, v1.y, acc.y);
        acc.z = fmaf(w1, v1.z, acc.z); acc.w = fmaf(w1, v1.w, acc.w);
    }
    if (j < end) {
        int s0 = esrc[j];
        float w0 = ew2[j];
        float4 v0 = *reinterpret_cast<const float4*>(feat + (size_t)s0 * HID + col);
        acc.x = fmaf(w0, v0.x, acc.x); acc.y = fmaf(w0, v0.y, acc.y);
        acc.z = fmaf(w0, v0.z, acc.z); acc.w = fmaf(w0, v0.w, acc.w);
    }
    *reinterpret_cast<float4*>(out + (size_t)node * HID + col) = acc;
}

__global__ __launch_bounds__(128)
void aggr64_kernel(const float* __restrict__ feat,
                   const int* __restrict__ rowptr, const int* __restrict__ esrc,
                   const float* __restrict__ ew2, __half* __restrict__ out, int N,
                   float* __restrict__ sums) {
    if (blockIdx.x == 0) {
        for (int i = threadIdx.x; i < 2 * HID; i += 128) sums[i] = 0.f;
    }
    int node = blockIdx.x * 8 + (threadIdx.x >> 4);
    if (node >= N) return;
    int col = (threadIdx.x & 15) * 4;
    int beg = rowptr[node], end = rowptr[node + 1];
    float4 acc = make_float4(0.f, 0.f, 0.f, 0.f);
    for (int j = beg; j < end; j++) {
        int s = esrc[j];
        float w = ew2[j];
        float4 v = *reinterpret_cast<const float4*>(feat + (size_t)s * INCH + col);
        acc.x = fmaf(w, v.x, acc.x); acc.y = fmaf(w, v.y, acc.y);
        acc.z = fmaf(w, v.z, acc.z); acc.w = fmaf(w, v.w, acc.w);
    }
    *reinterpret_cast<__half2*>(out + afrag(node, col,     4)) = __floats2half2_rn(acc.x, acc.y);
    *reinterpret_cast<__half2*>(out + afrag(node, col + 2, 4)) = __floats2half2_rn(acc.z, acc.w);
}

// ---------------- fp16 tensor-core GEMM, cp.async 3-stage, 64x64 warp tiles ----------------
#define CP_A16(dst, src) asm volatile("cp.async.cg.shared.global [%0], [%1], 16;" :: "r"(dst), "l"(src))
#define CP_B8(dst, src)  asm volatile("cp.async.ca.shared.global [%0], [%1], 8;"  :: "r"(dst), "l"(src))
#define CP_COMMIT()      asm volatile("cp.async.commit_group;" ::: "memory")
#define CP_WAIT1()       asm volatile("cp.async.wait_group 1;" ::: "memory")

template <int MODE>   // 0 = plain, 1 = +bias
__global__ __launch_bounds__(128, 2)
void hgemm_kernel(const __half* __restrict__ A, const __half* __restrict__ Bt,
                  float* __restrict__ C, const float* __restrict__ bias,
                  int M, int Kt, int ldc) {
    __shared__ uint32_t As[3][16 * 128];
    __shared__ uint32_t Bs[3][32 * 64];

    const int tid  = threadIdx.x;
    const int lane = tid & 31;
    const int warp = tid >> 5;
    const int bm = blockIdx.y * 128;
    const int bn = blockIdx.x * 128;
    const int wm = (warp >> 1) * 64;
    const int wn = (warp & 1) * 64;
    const int mtBase = bm >> 4;
    const int ntBase = bn >> 3;
    const int T = Kt >> 1;

    float acc[4][8][4];
#pragma unroll
    for (int i = 0; i < 4; i++)
#pragma unroll
        for (int j = 0; j < 8; j++)
#pragma unroll
            for (int k = 0; k < 4; k++) acc[i][j][k] = 0.f;

    auto issue = [&](int t, int stage) {
#pragma unroll
        for (int it = 0; it < 4; it++) {
            int p = tid + it * 128;
            int fi = p >> 5, ln = p & 31;
            const __half* src = A + ((((size_t)(mtBase + (fi >> 1)) * Kt) + (2 * t + (fi & 1))) * 32 + ln) * 8;
            CP_A16(smem_u32(&As[stage][fi * 128 + ln * 4]), src);
        }
#pragma unroll
        for (int it = 0; it < 8; it++) {
            int p = tid + it * 128;
            int fi = p >> 5, ln = p & 31;
            const __half* src = Bt + ((((size_t)(ntBase + (fi >> 1)) * Kt) + (2 * t + (fi & 1))) * 32 + ln) * 4;
            CP_B8(smem_u32(&Bs[stage][fi * 64 + ln * 2]), src);
        }
    };
    auto compute = [&](int buf) {
#pragma unroll
        for (int kt = 0; kt < 2; kt++) {
            uint32_t af[4][4];
#pragma unroll
            for (int mi = 0; mi < 4; mi++) {
                int fi = ((wm >> 4) + mi) * 2 + kt;
                uint4 v = *reinterpret_cast<const uint4*>(&As[buf][fi * 128 + lane * 4]);
                af[mi][0] = v.x; af[mi][1] = v.y; af[mi][2] = v.z; af[mi][3] = v.w;
            }
            uint32_t bf[8][2];
#pragma unroll
            for (int ni = 0; ni < 8; ni++) {
                int fi = ((wn >> 3) + ni) * 2 + kt;
                uint2 v = *reinterpret_cast<const uint2*>(&Bs[buf][fi * 64 + lane * 2]);
                bf[ni][0] = v.x; bf[ni][1] = v.y;
            }
#pragma unroll
            for (int mi = 0; mi < 4; mi++)
#pragma unroll
                for (int ni = 0; ni < 8; ni++) {
                    asm volatile(
                        "mma.sync.aligned.m16n8k16.row.col.f32.f16.f16.f32 "
                        "{%0,%1,%2,%3}, {%4,%5,%6,%7}, {%8,%9}, {%0,%1,%2,%3};\n"
                        : "+f"(acc[mi][ni][0]), "+f"(acc[mi][ni][1]),
                          "+f"(acc[mi][ni][2]), "+f"(acc[mi][ni][3])
                        : "r"(af[mi][0]), "r"(af[mi][1]), "r"(af[mi][2]), "r"(af[mi][3]),
                          "r"(bf[ni][0]), "r"(bf[ni][1]));
                }
        }
    };

    issue(0, 0);
    CP_COMMIT();
    if (T > 1) issue(1, 1);
    CP_COMMIT();
    for (int t = 0; t < T; t++) {
        CP_WAIT1();
        __syncthreads();
        if (t + 2 < T) issue(t + 2, (t + 2) % 3);
        CP_COMMIT();
        compute(t % 3);
    }

    const int gq = lane >> 2;
    const int rr = (lane & 3) << 1;
#pragma unroll
    for (int mi = 0; mi < 4; mi++) {
#pragma unroll
        for (int ni = 0; ni < 8; ni++) {
            int col = bn + wn + ni * 8 + rr;
#pragma unroll
            for (int h = 0; h < 2; h++) {
                int r = bm + wm + mi * 16 + gq + h * 8;
                if (r < M) {
                    float2 v = make_float2(acc[mi][ni][h * 2], acc[mi][ni][h * 2 + 1]);
                    if (MODE == 1) { v.x += bias[col]; v.y += bias[col + 1]; }
                    *reinterpret_cast<float2*>(C + (size_t)r * ldc + col) = v;
                }
            }
        }
    }
}

// ---------------- BN / elementwise ----------------
__global__ void bn_stats_kernel(const float* __restrict__ x, float* __restrict__ sums,
                                int Nrows, int C) {
    int col = threadIdx.x;
    int rowsPerBlock = (Nrows + gridDim.x - 1) / gridDim.x;
    int r0 = blockIdx.x * rowsPerBlock;
    int r1 = min(Nrows, r0 + rowsPerBlock);
    float s = 0.f, s2 = 0.f;
    for (int r = r0; r < r1; r++) {
        float v = x[(size_t)r * C + col];
        s += v;
        s2 = fmaf(v, v, s2);
    }
    atomicAdd(&sums[col], s);
    atomicAdd(&sums[C + col], s2);
}

__global__ void bn_apply_relu_kernel(const float* __restrict__ x,
                                     __half* __restrict__ hh, __half* __restrict__ dual,
                                     const float* __restrict__ sums,
                                     const float* __restrict__ gamma,
                                     const float* __restrict__ beta,
                                     int N, float invN) {
    int idx = blockIdx.x * blockDim.x + threadIdx.x;
    if (idx >= N * 256) return;
    int row = idx >> 8;
    int col = (idx & 255) << 1;
    float2 xv = reinterpret_cast<const float2*>(x)[idx];
    float mu0  = sums[col] * invN,  mu1 = sums[col + 1] * invN;
    float var0 = sums[HID + col] * invN - mu0 * mu0;
    float var1 = sums[HID + col + 1] * invN - mu1 * mu1;
    float v0 = (xv.x - mu0) * (gamma[col] * rsqrtf(var0 + 1e-5f)) + beta[col];
    float v1 = (xv.y - mu1) * (gamma[col + 1] * rsqrtf(var1 + 1e-5f)) + beta[col + 1];
    __half2 h = __floats2half2_rn(fmaxf(v0, 0.f), fmaxf(v1, 0.f));
    *reinterpret_cast<__half2*>(hh + afrag(row, col, 32)) = h;
    if (dual) *reinterpret_cast<__half2*>(dual + afrag(row, col, 64)) = h;
}

// layer0: gates layout [i|g|o] stride 1536; c = sigmoid(i)*tanh(g)
__global__ void cell0a_kernel(const float* __restrict__ gates, float* __restrict__ c,
                              __half* __restrict__ ch, int N) {
    int idx = blockIdx.x * blockDim.x + threadIdx.x;
    if (idx >= N * 256) return;
    int row = idx >> 8;
    int col = (idx & 255) << 1;
    const float* g = gates + (size_t)row * 1536;
    float2 iv = *reinterpret_cast<const float2*>(g + col);
    float2 gv = *reinterpret_cast<const float2*>(g + 512 + col);
    float v0 = sigmoidf_(iv.x) * tanhf(gv.x);
    float v1 = sigmoidf_(iv.y) * tanhf(gv.y);
    *reinterpret_cast<float2*>(c + (size_t)row * HID + col) = make_float2(v0, v1);
    *reinterpret_cast<__half2*>(ch + afrag(row, col, 32)) = __floats2half2_rn(v0, v1);
}

// ht = sigmoid(o + opeep) * tanh(c); og = o-gate base, ldg = gate row stride
template <int L>
__global__ void cell_ob_kernel(const float* __restrict__ og, int ldg,
                               const float* __restrict__ op, const float* __restrict__ c,
                               float* __restrict__ ht, __half* __restrict__ dual, int N) {
    int idx = blockIdx.x * blockDim.x + threadIdx.x;
    if (idx >= N * 256) return;
    int row = idx >> 8;
    int col = (idx & 255) << 1;
    float2 ov = *reinterpret_cast<const float2*>(og + (size_t)row * ldg + col);
    float2 pv = *reinterpret_cast<const float2*>(op + (size_t)row * HID + col);
    float2 cv = *reinterpret_cast<const float2*>(c + (size_t)row * HID + col);
    float v0 = sigmoidf_(ov.x + pv.x) * tanhf(cv.x);
    float v1 = sigmoidf_(ov.y + pv.y) * tanhf(cv.y);
    if (L == 0)
        *reinterpret_cast<__half2*>(dual + afrag(row, 512 + col, 64)) = __floats2half2_rn(v0, v1);
    else
        *reinterpret_cast<float2*>(ht + (size_t)row * HID + col) = make_float2(v0, v1);
}

// layer1: c <- f*c + i*g (with peepholes); write c fp32 + ch fp16
__global__ void cell1a_kernel(const float* __restrict__ gates, const float* __restrict__ cp,
                              float* __restrict__ c, __half* __restrict__ ch, int N) {
    int idx = blockIdx.x * blockDim.x + threadIdx.x;
    if (idx >= N * 256) return;
    int row = idx >> 8;
    int col = (idx & 255) << 1;
    const float* g = gates + (size_t)row * 2048;
    float2 iv = *reinterpret_cast<const float2*>(g + col);
    float2 fv = *reinterpret_cast<const float2*>(g + 512 + col);
    float2 gv = *reinterpret_cast<const float2*>(g + 1024 + col);
    float2 pg = *reinterpret_cast<const float2*>(cp + (size_t)row * 1024 + col);
    float2 pf = *reinterpret_cast<const float2*>(cp + (size_t)row * 1024 + 512 + col);
    float2 cv = *reinterpret_cast<const float2*>(c + (size_t)row * HID + col);
    float v0 = sigmoidf_(fv.x + pf.x) * cv.x + sigmoidf_(iv.x) * tanhf(gv.x + pg.x);
    float v1 = sigmoidf_(fv.y + pf.y) * cv.y + sigmoidf_(iv.y) * tanhf(gv.y + pg.y);
    *reinterpret_cast<float2*>(c + (size_t)row * HID + col) = make_float2(v0, v1);
    *reinterpret_cast<__half2*>(ch + afrag(row, col, 32)) = __floats2half2_rn(v0, v1);
}

// ---------------- output projection: warp per row, B transposed in smem ----------------
__global__ __launch_bounds__(256)
void outproj_kernel(const float* __restrict__ A, const float* __restrict__ B,
                    float* __restrict__ C, const float* __restrict__ bias, int M) {
    __shared__ float Bs[NPRED * HID];
    int tid = threadIdx.x;
    for (int i = tid; i < NPRED * HID; i += 256) {
        int k = i / NPRED, c = i % NPRED;
        Bs[c * HID + k] = B[i];
    }
    __syncthreads();
    int warp = tid >> 5, lane = tid & 31;
    int row = blockIdx.x * 8 + warp;
    if (row >= M) return;
    const float* a = A + (size_t)row * HID;
    float acc[NPRED];
#pragma unroll
    for (int c = 0; c < NPRED; c++) acc[c] = 0.f;
#pragma unroll
    for (int kk = 0; kk < 16; kk++) {
        int k = kk * 32 + lane;
        float av = a[k];
#pragma unroll
        for (int c = 0; c < NPRED; c++)
            acc[c] = fmaf(av, Bs[c * HID + k], acc[c]);
    }
#pragma unroll
    for (int c = 0; c < NPRED; c++)
#pragma unroll
        for (int o = 16; o > 0; o >>= 1)
            acc[c] += __shfl_down_sync(0xFFFFFFFFu, acc[c], o);
    if (lane == 0) {
#pragma unroll
        for (int c = 0; c < NPRED; c++)
            C[(size_t)row * NPRED + c] = acc[c] + bias[c];
    }
}

// ---------------- host orchestration ----------------
static inline void run_hgemm_s(const __half* A, const __half* Bt, float* C, const float* bias,
                               int M, int Nc, int Kt, int ldc, int mode, cudaStream_t st) {
    dim3 grid(Nc / 128, (M + 127) / 128);
    if (mode == 1)
        hgemm_kernel<1><<<grid, 128, 0, st>>>(A, Bt, C, bias, M, Kt, ldc);
    else
        hgemm_kernel<0><<<grid, 128, 0, st>>>(A, Bt, C, bias, M, Kt, ldc);
}
static inline void run_hgemm(const __half* A, const __half* Bt, float* C, const float* bias,
                             int M, int Nc, int Kt, int ldc, int mode) {
    run_hgemm_s(A, Bt, C, bias, M, Nc, Kt, ldc, mode, 0);
}

extern "C" void kernel_launch(void* const* d_in, const int* in_sizes, int n_in,
                              void* d_out, int out_size) {
    const float* x        = (const float*)d_in[0];
    const int*   ei       = (const int*)  d_in[1];
    const float* ew       = (const float*)d_in[2];
    const float* gcn0_W   = (const float*)d_in[3];
    const float* gcn_W    = (const float*)d_in[5];
    const float* bn_gamma = (const float*)d_in[7];
    const float* bn_beta  = (const float*)d_in[8];
    const float* w_ih     = (const float*)d_in[9];
    const float* w_hh     = (const float*)d_in[10];
    const float* w_ch     = (const float*)d_in[11];
    const float* lstm_b   = (const float*)d_in[12];
    const float* out_W    = (const float*)d_in[13];
    const float* out_b    = (const float*)d_in[14];
    float* out = (float*)d_out;

    const int N = in_sizes[0] / INCH;
    const int E = in_sizes[2];
    const int* src = ei;
    const int* dst = ei + E;
    const float invN = 1.f / (float)N;

    float *p_t, *p_agg, *p_gates, *p_c, *p_ht, *p_peep, *p_sums, *p_ew2, *p_biaspk;
    __half *p_wt, *p_axh, *p_hh, *p_ch, *p_dual;
    int *p_deg, *p_fill, *p_rowptr, *p_esrc;
    cudaGetSymbolAddress((void**)&p_t,     g_t);
    cudaGetSymbolAddress((void**)&p_agg,   g_agg);
    cudaGetSymbolAddress((void**)&p_gates, g_gates);
    cudaGetSymbolAddress((void**)&p_c,     g_c);
    cudaGetSymbolAddress((void**)&p_ht,    g_ht);
    cudaGetSymbolAddress((void**)&p_peep,  g_peep);
    cudaGetSymbolAddress((void**)&p_sums,  g_bnsums);
    cudaGetSymbolAddress((void**)&p_biaspk,g_biaspk);
    cudaGetSymbolAddress((void**)&p_wt,    g_wt);
    cudaGetSymbolAddress((void**)&p_axh,   g_axh);
    cudaGetSymbolAddress((void**)&p_hh,    g_hh);
    cudaGetSymbolAddress((void**)&p_ch,    g_ch);
    cudaGetSymbolAddress((void**)&p_dual,  g_dual);
    cudaGetSymbolAddress((void**)&p_deg,   g_deg);
    cudaGetSymbolAddress((void**)&p_fill,  g_fill);
    cudaGetSymbolAddress((void**)&p_rowptr,g_rowptr);
    cudaGetSymbolAddress((void**)&p_esrc,  g_esrc);
    cudaGetSymbolAddress((void**)&p_ew2,   g_ew2);

    const int blkNH2 = (N * 256 + 255) / 256;
    const int bnStatBlocks = 160;
    const int eBlocks = (E + 255) / 256;
    const float* wch1 = w_ch + (size_t)HID * 3 * HID;

    // ---- build fused pack descriptor table ----
    PackArgs pa;
    {
        int b = 0, i = 0;
        auto seg = [&](const float* W, int ldw, int outOff, int KtTot, int ktBase,
                       int K, int Nn) {
            pa.d[i++] = {W, ldw, outOff, KtTot, ktBase, K, Nn, b};
            b += Nn * K / 4;
        };
        seg(gcn0_W, HID, WT_GCN0, 4, 0, INCH, 512);
        seg(gcn_W,             HID, WT_GCN1, 32, 0, HID, 512);
        seg(gcn_W + HID * HID, HID, WT_GCN2, 32, 0, HID, 512);
        seg(w_ih,        4 * HID, WT_IH0,              32, 0, HID, 512);
        seg(w_ih + 1024, 4 * HID, WT_IH0 + 64 * 4096,  32, 0, HID, 512);
        seg(w_ih + 1536, 4 * HID, WT_IH0 + 128 * 4096, 32, 0, HID, 512);
        seg(w_ih + (size_t)HID * 4 * HID, 4 * HID, WT_IHHH1, 64, 0,  HID, 4 * HID);
        seg(w_hh + (size_t)HID * 4 * HID, 4 * HID, WT_IHHH1, 64, 32, HID, 4 * HID);
        seg(w_ch + 2 * HID, 3 * HID, WT_CH0_O,  32, 0, HID, 512);
        seg(wch1,           3 * HID, WT_CH1_FG, 32, 0, HID, 1024);
        seg(wch1 + 2 * HID, 3 * HID, WT_CH1_O,  32, 0, HID, 512);
        pa.total = b;
    }
    const int packBlocks = (pa.total + 255) / 256;
    const bool dual_stream = (g_sh.s != nullptr);

    // ---- fork 1: weight packs on side stream, CSR + aggr64 on main ----
    if (dual_stream) {
        cudaEventRecord(g_sh.evFork, 0);
        cudaStreamWaitEvent(g_sh.s, g_sh.evFork, 0);
        packAll_kernel<<<packBlocks, 256, 0, g_sh.s>>>(pa, p_wt);
        pack_bias_kernel<<<6, 256, 0, g_sh.s>>>(lstm_b, p_biaspk);
    } else {
        packAll_kernel<<<packBlocks, 256>>>(pa, p_wt);
        pack_bias_kernel<<<6, 256>>>(lstm_b, p_biaspk);
    }

    // CSR build + input aggregation (main stream)
    zero2_int_kernel<<<(N + 255) / 256, 256>>>(p_deg, p_fill, N);
    hist_kernel<<<eBlocks, 256>>>(dst, p_deg, E);
    scan_kernel<<<1, 1024>>>(p_deg, p_rowptr, N);
    fill_kernel<<<eBlocks, 256>>>(src, dst, ew, p_rowptr, p_fill, p_esrc, p_ew2, E);
    aggr64_kernel<<<(N + 7) / 8, 128>>>(x, p_rowptr, p_esrc, p_ew2, p_axh, N, p_sums);

    if (dual_stream) {
        cudaEventRecord(g_sh.evJoin, g_sh.s);
        cudaStreamWaitEvent(0, g_sh.evJoin, 0);
    }

    // ---- GCN layer 0 ----
    run_hgemm(p_axh, p_wt + WT_GCN0, p_t, nullptr, N, HID, 4, HID, 0);
    bn_stats_kernel<<<bnStatBlocks, HID>>>(p_t, p_sums, N, HID);
    bn_apply_relu_kernel<<<blkNH2, 256>>>(p_t, p_hh, nullptr, p_sums,
                                          bn_gamma, bn_beta, N, invN);

    // ---- GCN layers 1..2 ----
    for (int l = 0; l < 2; l++) {
        run_hgemm(p_hh, p_wt + (l == 0 ? WT_GCN1 : WT_GCN2), p_t, nullptr, N, HID, 32, HID, 0);
        aggr512_kernel<<<N, 128>>>(p_t, p_rowptr, p_esrc, p_ew2, p_agg, p_sums);
        bn_stats_kernel<<<bnStatBlocks, HID>>>(p_agg, p_sums, N, HID);
        bn_apply_relu_kernel<<<blkNH2, 256>>>(p_agg, p_hh, (l == 1) ? p_dual : nullptr,
                                              p_sums, bn_gamma + (l + 1) * HID,
                                              bn_beta + (l + 1) * HID, N, invN);
    }

    // ---- LSTM layer 0 (h0 = c0 = 0; gates [i|g|o], f skipped) ----
    run_hgemm(p_hh, p_wt + WT_IH0, p_gates, p_biaspk, N, 1536, 32, 1536, 1);
    cell0a_kernel<<<blkNH2, 256>>>(p_gates, p_c, p_ch, N);

    // ---- fork 2: FG-peephole GEMM (needs only ch) on side stream ----
    if (dual_stream) {
        cudaEventRecord(g_sh.evFork2, 0);
        cudaStreamWaitEvent(g_sh.s, g_sh.evFork2, 0);
        run_hgemm_s(p_ch, p_wt + WT_CH1_FG, p_peep, nullptr, N, 2 * HID, 32, 2 * HID, 0, g_sh.s);
    }

    // main: o-peephole(L0) -> g_agg; h0; L1 gates GEMM
    run_hgemm(p_ch, p_wt + WT_CH0_O, p_agg, nullptr, N, HID, 32, HID, 0);
    cell_ob_kernel<0><<<blkNH2, 256>>>(p_gates + 1024, 1536, p_agg, p_c,
                                       nullptr, p_dual, N);
    run_hgemm(p_dual, p_wt + WT_IHHH1, p_gates, lstm_b + 4 * HID, N, 4 * HID, 64, 4 * HID, 1);

    if (dual_stream) {
        cudaEventRecord(g_sh.evJoin2, g_sh.s);
        cudaStreamWaitEvent(0, g_sh.evJoin2, 0);
    } else {
        run_hgemm(p_ch, p_wt + WT_CH1_FG, p_peep, nullptr, N, 2 * HID, 32, 2 * HID, 0);
    }

    // ---- LSTM layer 1 cell + o-peephole + h1 ----
    cell1a_kernel<<<blkNH2, 256>>>(p_gates, p_peep, p_c, p_ch, N);
    run_hgemm(p_ch, p_wt + WT_CH1_O, p_peep, nullptr, N, HID, 32, HID, 0);
    cell_ob_kernel<1><<<blkNH2, 256>>>(p_gates + 1536, 2048, p_peep, p_c,
                                       p_ht, nullptr, N);

    // ---- output projection ----
    outproj_kernel<<<(N + 7) / 8, 256>>>(p_ht, out_W, out, out_b, N);
}